// round 8
// baseline (speedup 1.0000x reference)
#include <cuda_runtime.h>
#include <cstdint>

// NMS_20933670600803  — heatmap (B,1,14,14) f32 -> [m1 | m2] f32
//
// One warp per item, float4 I/O. Keys (validated R4-R7, rel_err 0):
//   key = (max(fb, bits(0.6f)) << 8) + (0xE66666FF - i)  [mod 2^32]
// below-threshold / suppressed -> key = 255 - i; unsigned max == jnp.argmax
// (max value, tie -> smallest index). Warp reduce = one REDUX.MAX.U32.
// Dead slots (i >= 196) load 0.0 -> key = 255-i <= 59 < 60 <= live keys.
//
// R8: byte-mask suppression table — per (peak bi, lane) two u32 words whose
// byte c is 0xFF iff element {4*lane+c, 128+4*lane+c} lies in bi's window.
// Per-element suppress = PRMT(replicate byte) + single LOP3(key & (~m|0xFF)).
// Emission moved onto the fma pipe (IMAD chains, sign*0x3F800000).

#define NPIX 196
#define NVEC 49
#define WPB  8
#define THREADS (WPB * 32)
#define KTHR 0x3F19999Au     // __float_as_uint(0.6f)

struct alignas(8) ByteTable {
    // w[bi][lane][0]: bytes for elements 4*lane..4*lane+3
    // w[bi][lane][1]: bytes for elements 128+4*lane..128+4*lane+3
    unsigned w[196][32][2];
    constexpr ByteTable() : w{} {
        for (int bi = 0; bi < 196; ++bi) {
            const int x = bi / 14, y = bi % 14;
            const int x1 = (x - 5 > 0) ? x - 5 : 0;
            const int x2 = (x + 5 < 15) ? x + 5 : 15;
            const int y1 = (y - 5 > 0) ? y - 5 : 0;
            const int y2 = (y + 5 < 15) ? y + 5 : 15;
            for (int lane = 0; lane < 32; ++lane)
                for (int half = 0; half < 2; ++half) {
                    unsigned word = 0;
                    for (int c = 0; c < 4; ++c) {
                        const int i = half * 128 + 4 * lane + c;
                        if (i < 196) {
                            const int eu = i / 14, ev = i % 14;
                            if (eu >= x1 && eu < x2 && ev >= y1 && ev < y2)
                                word |= 0xFFu << (8 * c);
                        }
                    }
                    w[bi][lane][half] = word;
                }
        }
    }
};
__constant__ ByteTable g_tbl;    // 50176 B, constexpr-initialized

__global__ __launch_bounds__(THREADS)
void nms_masks_kernel(const float4* __restrict__ hm,
                      float4* __restrict__ out,
                      int B)
{
    const int warp = blockIdx.x * WPB + (threadIdx.x >> 5);
    const int lane = threadIdx.x & 31;
    if (warp >= B) return;

    const float4* __restrict__ p = hm + (size_t)warp * NVEC;
    const float4 va = __ldcs(p + lane);            // elements 4j..4j+3
    const bool has2 = (lane < 17);
    float4 vb = make_float4(0.f, 0.f, 0.f, 0.f);
    if (has2) vb = __ldcs(p + lane + 32);          // elements 128+4j..

    const int i0 = 4 * lane;
    const int i1 = 128 + 4 * lane;

    unsigned key[8];
    {
        const float vals[8] = {va.x, va.y, va.z, va.w, vb.x, vb.y, vb.z, vb.w};
#pragma unroll
        for (int c = 0; c < 8; ++c) {
            const int i = (c < 4) ? (i0 + c) : (i1 + c - 4);
            const unsigned fb = __float_as_uint(vals[c]);
            const unsigned M  = (fb > KTHR) ? fb : KTHR;          // IMNMX.U32
            key[c] = M * 256u + (0xE66666FFu - (unsigned)i);      // IMAD (fma pipe)
        }
    }

    int bis[4];
#pragma unroll
    for (int it = 0; it < 4; ++it) {
        unsigned m = max(max(max(key[0], key[1]), max(key[2], key[3])),
                         max(max(key[4], key[5]), max(key[6], key[7])));
        const unsigned w = __reduce_max_sync(0xffffffffu, m);     // REDUX.MAX.U32
        const int bi = (int)((~w) & 0xFFu);                       // 255 - (w & 0xFF)
        bis[it] = bi;

        if (it < 3) {
            const uint2 t = *reinterpret_cast<const uint2*>(g_tbl.w[bi][lane]);
#pragma unroll
            for (int c = 0; c < 4; ++c) {
                const unsigned m0 = __byte_perm(t.x, 0u, 0x1111 * c); // PRMT: byte c -> all
                const unsigned m1 = __byte_perm(t.y, 0u, 0x1111 * c); // 0x00000000 / 0xFFFFFFFF
                key[c]     &= (~m0 | 0xFFu);   // single LOP3 each
                key[c + 4] &= (~m1 | 0xFFu);
            }
        }
    }

    // decode peaks after the loop (off the REDUX->LDC critical path)
    int px[4], py[4], pk[4];
#pragma unroll
    for (int t = 0; t < 4; ++t) {
        const int x = (bis[t] * 18725) >> 18;      // bi / 14 for bi < 256
        const int y = bis[t] - 14 * x;
        px[t] = x; py[t] = y; pk[t] = x | (y << 4);
    }

    // farthest pair among 4 peaks (6 pairs, first-tie argmax), packed key
    unsigned kbest = 0;
    {
        const int pa[6] = {0, 0, 0, 1, 1, 2};
        const int pb[6] = {1, 2, 3, 2, 3, 3};
#pragma unroll
        for (int q = 0; q < 6; ++q) {
            const int dx = px[pb[q]] - px[pa[q]];
            const int dy = py[pb[q]] - py[pa[q]];
            const int d  = dx * dx + dy * dy;      // <= 338
            const unsigned kd = ((unsigned)d << 20) | ((unsigned)(5 - q) << 16)
                              | (unsigned)(pk[pa[q]] | (pk[pb[q]] << 8));
            kbest = (kbest > kd) ? kbest : kd;
        }
    }
    const int ax = (int)(kbest & 0xFu);
    const int ay = (int)((kbest >> 4)  & 0xFu);
    const int bx = (int)((kbest >> 8)  & 0xFu);
    const int by = (int)((kbest >> 12) & 0xFu);

    // d1 - d2 = Cy*i + Cg*eu + mCc   (ev = i - 14*eu folded in)
    const int dxc = bx - ax, dyc = by - ay;
    const int Cy  = 2 * dyc;
    const int Cg  = 2 * dxc - 14 * Cy;
    const int mCc = -(dxc * (ax + bx) + dyc * (ay + by));

    float4* __restrict__ o1 = out + (size_t)warp * NVEC;
    float4* __restrict__ o2 = o1 + (size_t)B * NVEC;

    {
        float r1[4], r2[4];
#pragma unroll
        for (int c = 0; c < 4; ++c) {
            const int i  = i0 + c;
            const int eu = (i * 18725) >> 18;                       // IMAD + SHF
            const int pv = Cy * i + (Cg * eu + mCc);                // 2x IMAD (fma)
            const unsigned m1b = ((unsigned)pv >> 31) * 0x3F800000u; // SHF + IMAD
            r1[c] = __uint_as_float(m1b);                 // 1.0f if d1<d2
            r2[c] = __uint_as_float(m1b ^ 0x3F800000u);   // complement
        }
        __stcs(o1 + lane, make_float4(r1[0], r1[1], r1[2], r1[3]));
        __stcs(o2 + lane, make_float4(r2[0], r2[1], r2[2], r2[3]));
    }
    if (has2) {
        float r1[4], r2[4];
#pragma unroll
        for (int c = 0; c < 4; ++c) {
            const int i  = i1 + c;
            const int eu = (i * 18725) >> 18;
            const int pv = Cy * i + (Cg * eu + mCc);
            const unsigned m1b = ((unsigned)pv >> 31) * 0x3F800000u;
            r1[c] = __uint_as_float(m1b);
            r2[c] = __uint_as_float(m1b ^ 0x3F800000u);
        }
        __stcs(o1 + lane + 32, make_float4(r1[0], r1[1], r1[2], r1[3]));
        __stcs(o2 + lane + 32, make_float4(r2[0], r2[1], r2[2], r2[3]));
    }
}

extern "C" void kernel_launch(void* const* d_in, const int* in_sizes, int n_in,
                              void* d_out, int out_size)
{
    const float4* hm  = (const float4*)d_in[0];
    float4*       out = (float4*)d_out;
    const int B = in_sizes[0] / NPIX;              // 131072
    const int grid = (B + WPB - 1) / WPB;
    nms_masks_kernel<<<grid, THREADS>>>(hm, out, B);
}

// round 9
// speedup vs baseline: 3.6582x; 3.6582x over previous
#include <cuda_runtime.h>
#include <cstdint>

// NMS_20933670600803  — heatmap (B,1,14,14) f32 -> [m1 | m2] f32
//
// One warp per item, float4 I/O. Keys (validated R4-R8, rel_err 0):
//   key = (max(fb, bits(0.6f)) << 8) + (0xE66666FF - i)  [mod 2^32]
// below-threshold / suppressed -> key = 255 - i; unsigned max == jnp.argmax
// (max value, tie -> smallest index). Warp reduce = one REDUX.MAX.U32.
// Dead slots (i >= 196) load 0.0 -> key = 255-i <= 59 < 60 <= live keys.
//
// R9: byte-mask suppression table in GLOBAL memory (R8 put it in __constant__
// with per-lane divergent addresses -> 32-way LDC serialization -> 188us).
// For fixed peak bi, lanes 0..31 read 32 consecutive uint2 = one coalesced
// 256B LDG.64; table (49KB) stays L1-resident. Suppress = PRMT + LOP3.

#define NPIX 196
#define NVEC 49
#define WPB  8
#define THREADS (WPB * 32)
#define KTHR 0x3F19999Au     // __float_as_uint(0.6f)

struct alignas(16) ByteTable {
    // w[bi][lane][0]: mask bytes for elements 4*lane..4*lane+3
    // w[bi][lane][1]: mask bytes for elements 128+4*lane..128+4*lane+3
    unsigned w[196][32][2];
    constexpr ByteTable() : w{} {
        for (int bi = 0; bi < 196; ++bi) {
            const int x = bi / 14, y = bi % 14;
            const int x1 = (x - 5 > 0) ? x - 5 : 0;
            const int x2 = (x + 5 < 15) ? x + 5 : 15;
            const int y1 = (y - 5 > 0) ? y - 5 : 0;
            const int y2 = (y + 5 < 15) ? y + 5 : 15;
            for (int lane = 0; lane < 32; ++lane)
                for (int half = 0; half < 2; ++half) {
                    unsigned word = 0;
                    for (int c = 0; c < 4; ++c) {
                        const int i = half * 128 + 4 * lane + c;
                        if (i < 196) {
                            const int eu = i / 14, ev = i % 14;
                            if (eu >= x1 && eu < x2 && ev >= y1 && ev < y2)
                                word |= 0xFFu << (8 * c);
                        }
                    }
                    w[bi][lane][half] = word;
                }
        }
    }
};
__device__ const ByteTable g_tbl;    // global memory, constexpr-initialized

__global__ __launch_bounds__(THREADS)
void nms_masks_kernel(const float4* __restrict__ hm,
                      float4* __restrict__ out,
                      int B)
{
    const int warp = blockIdx.x * WPB + (threadIdx.x >> 5);
    const int lane = threadIdx.x & 31;
    if (warp >= B) return;

    const float4* __restrict__ p = hm + (size_t)warp * NVEC;
    const float4 va = __ldcs(p + lane);            // elements 4j..4j+3
    const bool has2 = (lane < 17);
    float4 vb = make_float4(0.f, 0.f, 0.f, 0.f);
    if (has2) vb = __ldcs(p + lane + 32);          // elements 128+4j..

    const int i0 = 4 * lane;
    const int i1 = 128 + 4 * lane;

    unsigned key[8];
    {
        const float vals[8] = {va.x, va.y, va.z, va.w, vb.x, vb.y, vb.z, vb.w};
#pragma unroll
        for (int c = 0; c < 8; ++c) {
            const int i = (c < 4) ? (i0 + c) : (i1 + c - 4);
            const unsigned fb = __float_as_uint(vals[c]);
            const unsigned M  = (fb > KTHR) ? fb : KTHR;          // IMNMX.U32
            key[c] = M * 256u + (0xE66666FFu - (unsigned)i);      // IMAD (fma pipe)
        }
    }

    int bis[4];
#pragma unroll
    for (int it = 0; it < 4; ++it) {
        unsigned m = max(max(max(key[0], key[1]), max(key[2], key[3])),
                         max(max(key[4], key[5]), max(key[6], key[7])));
        const unsigned w = __reduce_max_sync(0xffffffffu, m);     // REDUX.MAX.U32
        const int bi = (int)((~w) & 0xFFu);                       // 255 - (w & 0xFF)
        bis[it] = bi;

        if (it < 3) {
            // coalesced: 32 lanes read 32 consecutive uint2 (256B, L1-resident)
            const uint2 t = __ldg(reinterpret_cast<const uint2*>(g_tbl.w[bi][lane]));
#pragma unroll
            for (int c = 0; c < 4; ++c) {
                const unsigned m0 = __byte_perm(t.x, 0u, 0x1111 * c); // PRMT: byte c -> all 4
                const unsigned m1 = __byte_perm(t.y, 0u, 0x1111 * c); // 0x0 or 0xFFFFFFFF
                key[c]     &= (~m0 | 0xFFu);   // single LOP3 each
                key[c + 4] &= (~m1 | 0xFFu);
            }
        }
    }

    // decode peaks after the loop (off the REDUX->LDG critical path)
    int px[4], py[4], pk[4];
#pragma unroll
    for (int t = 0; t < 4; ++t) {
        const int x = (bis[t] * 18725) >> 18;      // bi / 14 for bi < 256
        const int y = bis[t] - 14 * x;
        px[t] = x; py[t] = y; pk[t] = x | (y << 4);
    }

    // farthest pair among 4 peaks (6 pairs, first-tie argmax), packed key
    unsigned kbest = 0;
    {
        const int pa[6] = {0, 0, 0, 1, 1, 2};
        const int pb[6] = {1, 2, 3, 2, 3, 3};
#pragma unroll
        for (int q = 0; q < 6; ++q) {
            const int dx = px[pb[q]] - px[pa[q]];
            const int dy = py[pb[q]] - py[pa[q]];
            const int d  = dx * dx + dy * dy;      // <= 338
            const unsigned kd = ((unsigned)d << 20) | ((unsigned)(5 - q) << 16)
                              | (unsigned)(pk[pa[q]] | (pk[pb[q]] << 8));
            kbest = (kbest > kd) ? kbest : kd;
        }
    }
    const int ax = (int)(kbest & 0xFu);
    const int ay = (int)((kbest >> 4)  & 0xFu);
    const int bx = (int)((kbest >> 8)  & 0xFu);
    const int by = (int)((kbest >> 12) & 0xFu);

    // d1 - d2 = Cy*i + Cg*eu + mCc   (ev = i - 14*eu folded in)
    const int dxc = bx - ax, dyc = by - ay;
    const int Cy  = 2 * dyc;
    const int Cg  = 2 * dxc - 14 * Cy;
    const int mCc = -(dxc * (ax + bx) + dyc * (ay + by));

    float4* __restrict__ o1 = out + (size_t)warp * NVEC;
    float4* __restrict__ o2 = o1 + (size_t)B * NVEC;

    {
        float r1[4], r2[4];
#pragma unroll
        for (int c = 0; c < 4; ++c) {
            const int i  = i0 + c;
            const int eu = (i * 18725) >> 18;                        // IMAD + SHF
            const int pv = Cy * i + (Cg * eu + mCc);                 // 2x IMAD (fma)
            const unsigned m1b = ((unsigned)pv >> 31) * 0x3F800000u; // SHF + IMAD
            r1[c] = __uint_as_float(m1b);                 // 1.0f if d1<d2
            r2[c] = __uint_as_float(m1b ^ 0x3F800000u);   // complement
        }
        __stcs(o1 + lane, make_float4(r1[0], r1[1], r1[2], r1[3]));
        __stcs(o2 + lane, make_float4(r2[0], r2[1], r2[2], r2[3]));
    }
    if (has2) {
        float r1[4], r2[4];
#pragma unroll
        for (int c = 0; c < 4; ++c) {
            const int i  = i1 + c;
            const int eu = (i * 18725) >> 18;
            const int pv = Cy * i + (Cg * eu + mCc);
            const unsigned m1b = ((unsigned)pv >> 31) * 0x3F800000u;
            r1[c] = __uint_as_float(m1b);
            r2[c] = __uint_as_float(m1b ^ 0x3F800000u);
        }
        __stcs(o1 + lane + 32, make_float4(r1[0], r1[1], r1[2], r1[3]));
        __stcs(o2 + lane + 32, make_float4(r2[0], r2[1], r2[2], r2[3]));
    }
}

extern "C" void kernel_launch(void* const* d_in, const int* in_sizes, int n_in,
                              void* d_out, int out_size)
{
    const float4* hm  = (const float4*)d_in[0];
    float4*       out = (float4*)d_out;
    const int B = in_sizes[0] / NPIX;              // 131072
    const int grid = (B + WPB - 1) / WPB;
    nms_masks_kernel<<<grid, THREADS>>>(hm, out, B);
}